// round 2
// baseline (speedup 1.0000x reference)
#include <cuda_runtime.h>
#include <math.h>

// Problem dims (fixed by the dataset)
#define BB 1024
#define TT 64
#define DD 512
#define HH 512
#define N4H 2048   // 4*H

// ---------------- device scratch (no allocations allowed) ----------------
__device__ float g_zx[134217728];  // [B, T, 4H] = 1024*64*2048  (X@W + bias)
__device__ float g_z[2097152];     // [B, 4H]    per-step h@U
__device__ float g_h[524288];      // [B, H]
__device__ float g_c[524288];      // [B, H]

// ---------------- fp32 register-tiled SGEMM: C = A@B (+bias) -------------
// BM=BN=128, BK=16, 256 threads, 8x8 per-thread microtile.
#define BM 128
#define BN 128
#define BK 16
#define TM 8
#define TN 8

template <bool ADD_BIAS>
__global__ __launch_bounds__(256) void sgemm_kernel(
    const float* __restrict__ A,   // [M, K] row-major
    const float* __restrict__ B,   // [K, N] row-major
    const float* __restrict__ bias,// [N] or nullptr
    float* __restrict__ C,         // [M, N] row-major
    int M, int N, int K)
{
    __shared__ float As[BK][BM];
    __shared__ float Bs[BK][BN];

    const int tid = threadIdx.x;
    const int bm = blockIdx.y * BM;
    const int bn = blockIdx.x * BN;

    // A tile loaders: 128 rows x 16 cols = 512 float4; 2 per thread
    const int a_row  = tid >> 2;          // 0..63 (+64)
    const int a_col4 = (tid & 3) * 4;     // 0,4,8,12
    // B tile loaders: 16 rows x 128 cols = 512 float4; 2 per thread
    const int b_row  = tid >> 5;          // 0..7 (+8)
    const int b_col4 = (tid & 31) * 4;    // 0..124

    const int ty = tid >> 4;              // 0..15
    const int tx = tid & 15;              // 0..15

    float acc[TM][TN];
    #pragma unroll
    for (int i = 0; i < TM; i++)
        #pragma unroll
        for (int j = 0; j < TN; j++)
            acc[i][j] = 0.0f;

    for (int k0 = 0; k0 < K; k0 += BK) {
        // load A tile, transpose into As[k][m]
        #pragma unroll
        for (int r = 0; r < 2; r++) {
            int row = a_row + r * 64;
            float4 v = *reinterpret_cast<const float4*>(
                &A[(size_t)(bm + row) * K + (k0 + a_col4)]);
            As[a_col4 + 0][row] = v.x;
            As[a_col4 + 1][row] = v.y;
            As[a_col4 + 2][row] = v.z;
            As[a_col4 + 3][row] = v.w;
        }
        // load B tile directly
        #pragma unroll
        for (int r = 0; r < 2; r++) {
            int row = b_row + r * 8;
            *reinterpret_cast<float4*>(&Bs[row][b_col4]) =
                *reinterpret_cast<const float4*>(
                    &B[(size_t)(k0 + row) * N + (bn + b_col4)]);
        }
        __syncthreads();

        #pragma unroll
        for (int kk = 0; kk < BK; kk++) {
            float a[TM], b[TN];
            #pragma unroll
            for (int i = 0; i < TM; i++) a[i] = As[kk][ty * TM + i];
            #pragma unroll
            for (int j = 0; j < TN; j++) b[j] = Bs[kk][tx * TN + j];
            #pragma unroll
            for (int i = 0; i < TM; i++)
                #pragma unroll
                for (int j = 0; j < TN; j++)
                    acc[i][j] += a[i] * b[j];
        }
        __syncthreads();
    }

    // epilogue
    #pragma unroll
    for (int i = 0; i < TM; i++) {
        int row = bm + ty * TM + i;
        #pragma unroll
        for (int j = 0; j < TN; j += 4) {
            int col = bn + tx * TN + j;
            float4 v;
            v.x = acc[i][j + 0];
            v.y = acc[i][j + 1];
            v.z = acc[i][j + 2];
            v.w = acc[i][j + 3];
            if (ADD_BIAS) {
                v.x += bias[col + 0];
                v.y += bias[col + 1];
                v.z += bias[col + 2];
                v.w += bias[col + 3];
            }
            *reinterpret_cast<float4*>(&C[(size_t)row * N + col]) = v;
        }
    }
}

// ---------------- fused gate / state-update kernel ------------------------
// z_total = g_zx[b, t, :] (+ g_z[b, :] when has_h)
// i,f,o = sigmoid; g = tanh; c' = f*c + i*g; h' = o*tanh(c')
__global__ __launch_bounds__(256) void lstm_step_kernel(
    int t, int has_h, float* __restrict__ out)
{
    int idx = blockIdx.x * blockDim.x + threadIdx.x;  // 0 .. B*H-1
    int b = idx >> 9;        // /512
    int k = idx & 511;

    size_t zx_base = ((size_t)b * TT + t) * N4H;
    float zi = g_zx[zx_base + 0 * HH + k];
    float zf = g_zx[zx_base + 1 * HH + k];
    float zg = g_zx[zx_base + 2 * HH + k];
    float zo = g_zx[zx_base + 3 * HH + k];
    float cp = 0.0f;
    if (has_h) {
        size_t zh_base = (size_t)b * N4H;
        zi += g_z[zh_base + 0 * HH + k];
        zf += g_z[zh_base + 1 * HH + k];
        zg += g_z[zh_base + 2 * HH + k];
        zo += g_z[zh_base + 3 * HH + k];
        cp = g_c[idx];
    }

    float i = 1.0f / (1.0f + expf(-zi));
    float f = 1.0f / (1.0f + expf(-zf));
    float g = tanhf(zg);
    float o = 1.0f / (1.0f + expf(-zo));

    float cn = f * cp + i * g;
    float hn = o * tanhf(cn);

    g_c[idx] = cn;
    g_h[idx] = hn;
    out[((size_t)b * TT + t) * HH + k] = hn;
}

// ---------------- launch --------------------------------------------------
extern "C" void kernel_launch(void* const* d_in, const int* in_sizes, int n_in,
                              void* d_out, int out_size)
{
    const float* X    = (const float*)d_in[0];  // [B, T, D]
    const float* W    = (const float*)d_in[1];  // [D, 4H]
    const float* U    = (const float*)d_in[2];  // [H, 4H]
    const float* bias = (const float*)d_in[3];  // [4H]
    float* out = (float*)d_out;                 // [B, T, H]

    float *zx_p, *z_p, *h_p;
    cudaGetSymbolAddress((void**)&zx_p, g_zx);
    cudaGetSymbolAddress((void**)&z_p,  g_z);
    cudaGetSymbolAddress((void**)&h_p,  g_h);

    // Phase 1: Zx = X@W + bias   (M = B*T = 65536, N = 2048, K = 512)
    {
        dim3 grid(N4H / BN, (BB * TT) / BM);
        sgemm_kernel<true><<<grid, 256>>>(X, W, bias, zx_p, BB * TT, N4H, DD);
    }

    const int elem_blocks = (BB * HH) / 256;

    // t = 0: h=0, c=0 -> no recurrent GEMM needed
    lstm_step_kernel<<<elem_blocks, 256>>>(0, 0, out);

    // t = 1..63: z = h@U, then fused gate update
    dim3 grid2(N4H / BN, BB / BM);  // (16, 8) = 128 CTAs
    for (int t = 1; t < TT; t++) {
        sgemm_kernel<false><<<grid2, 256>>>(h_p, U, nullptr, z_p, BB, N4H, HH);
        lstm_step_kernel<<<elem_blocks, 256>>>(t, 1, out);
    }
}

// round 5
// speedup vs baseline: 2.6447x; 2.6447x over previous
#include <cuda_runtime.h>
#include <cuda_bf16.h>
#include <cstdint>
#include <math.h>

// Problem dims (fixed)
#define BB 1024
#define TT 64
#define DD 512
#define HH 512
#define N4H 2048
#define KBIG 1536   // 3*512 split-K
#define KHL  1024   // hi|lo storage per row

// ---------------- device scratch ----------------
__device__ float g_zx[134217728];                  // [65536, 2048] X@W + bias
__device__ float g_z[2097152];                     // [1024, 2048] per-step h@U
__device__ float g_c[524288];                      // [1024, 512]
__device__ __nv_bfloat16 g_xhl[67108864];          // [65536, 1024] hi|lo of X
__device__ __nv_bfloat16 g_wb[3145728];            // [2048, 1536]  W^T split
__device__ __nv_bfloat16 g_ub[3145728];            // [2048, 1536]  U^T split
__device__ __nv_bfloat16 g_hhl[1048576];           // [1024, 1024]  hi|lo of h

// ---------------- helpers ----------------
#define SW128(x) ((x) ^ (((x) >> 3) & 0x70))

__device__ __forceinline__ uint32_t smem_u32(const void* p) {
    uint32_t a;
    asm("{ .reg .u64 t; cvta.to.shared.u64 t, %1; cvt.u32.u64 %0, t; }" : "=r"(a) : "l"(p));
    return a;
}
__device__ __forceinline__ void cp_async16(uint32_t dst, const void* src) {
    asm volatile("cp.async.cg.shared.global [%0], [%1], 16;" :: "r"(dst), "l"(src));
}
#define CP_COMMIT() asm volatile("cp.async.commit_group;" ::: "memory")
#define CP_WAIT1()  asm volatile("cp.async.wait_group 1;" ::: "memory")
#define CP_WAIT0()  asm volatile("cp.async.wait_group 0;" ::: "memory")

__device__ __forceinline__ void ldsm_x4(uint32_t& r0, uint32_t& r1, uint32_t& r2, uint32_t& r3,
                                        uint32_t addr) {
    asm volatile("ldmatrix.sync.aligned.m8n8.x4.shared.b16 {%0,%1,%2,%3}, [%4];"
                 : "=r"(r0), "=r"(r1), "=r"(r2), "=r"(r3) : "r"(addr));
}
__device__ __forceinline__ void mma_bf16(float* c, const uint32_t* a, const uint32_t* b) {
    asm volatile(
        "mma.sync.aligned.m16n8k16.row.col.f32.bf16.bf16.f32 "
        "{%0,%1,%2,%3}, {%4,%5,%6,%7}, {%8,%9}, {%0,%1,%2,%3};"
        : "+f"(c[0]), "+f"(c[1]), "+f"(c[2]), "+f"(c[3])
        : "r"(a[0]), "r"(a[1]), "r"(a[2]), "r"(a[3]), "r"(b[0]), "r"(b[1]));
}

// ---------------- split-K bf16 warp-MMA GEMM ----------------
// C[M, 2048] (+bias) = A_hl @ Bt^T, K_eff = 1536, TN layout.
// A_hl: [M, 1024] bf16 (cols 0-511 = hi, 512-1023 = lo)
// Bt:   [2048, 1536] bf16 rows = N, K segments [hi | lo | hi]
// A k-chunk mapping: chunks 0-15 -> hi cols, 16-23 -> lo cols.
#define NCHUNK 24
#define STAGE_BYTES 32768   // 16KB A + 16KB B per stage

template <bool ADD_BIAS>
__global__ __launch_bounds__(256) void gemm3_kernel(
    const __nv_bfloat16* __restrict__ A,
    const __nv_bfloat16* __restrict__ Bt,
    const float* __restrict__ bias,
    float* __restrict__ C)
{
    extern __shared__ char dyn[];
    uint32_t dbase = smem_u32(dyn);
    dbase = (dbase + 1023u) & ~1023u;

    const int tid  = threadIdx.x;
    const int lane = tid & 31;
    const int wid  = tid >> 5;
    const int warp_m = wid >> 2;        // 0..1
    const int warp_n = wid & 3;         // 0..3
    const int wm = warp_m * 64;
    const int wn = warp_n * 32;
    const int bm = blockIdx.y * 128;
    const int bn = blockIdx.x * 128;

    const int g = lane >> 3;            // ldmatrix group 0..3
    const int r = lane & 7;

    float acc[4][4][4];
    #pragma unroll
    for (int i = 0; i < 4; i++)
        #pragma unroll
        for (int j = 0; j < 4; j++)
            #pragma unroll
            for (int k = 0; k < 4; k++)
                acc[i][j][k] = 0.0f;

    // ---- stage loader ----
    auto issue_load = [&](int stage, int c) {
        const int seg  = c >> 3;
        const int acol = ((seg == 2) ? 512 : 0) + (c & 7) * 64;
        const int bcol = c * 64;
        const uint32_t sA = dbase + stage * STAGE_BYTES;
        const uint32_t sB = sA + 16384;
        #pragma unroll
        for (int j = 0; j < 4; j++) {
            int i = tid + j * 256;
            int row = i >> 3, c16 = i & 7;
            cp_async16(sA + SW128((uint32_t)(row * 128 + c16 * 16)),
                       A + (size_t)(bm + row) * KHL + acol + c16 * 8);
        }
        #pragma unroll
        for (int j = 0; j < 4; j++) {
            int i = tid + j * 256;
            int row = i >> 3, c16 = i & 7;
            cp_async16(sB + SW128((uint32_t)(row * 128 + c16 * 16)),
                       Bt + (size_t)(bn + row) * KBIG + bcol + c16 * 8);
        }
    };

    issue_load(0, 0); CP_COMMIT();
    issue_load(1, 1); CP_COMMIT();

    for (int c = 0; c < NCHUNK; c++) {
        if (c < NCHUNK - 1) { CP_WAIT1(); } else { CP_WAIT0(); }
        __syncthreads();

        const uint32_t sA = dbase + (c & 1) * STAGE_BYTES;
        const uint32_t sB = sA + 16384;

        #pragma unroll
        for (int kk = 0; kk < 4; kk++) {
            uint32_t af[4][4];
            #pragma unroll
            for (int mi = 0; mi < 4; mi++) {
                int row = wm + mi * 16 + (g & 1) * 8 + r;
                int col = kk * 16 + (g >> 1) * 8;
                ldsm_x4(af[mi][0], af[mi][1], af[mi][2], af[mi][3],
                        sA + SW128((uint32_t)(row * 128 + col * 2)));
            }
            uint32_t bf[4][2];
            #pragma unroll
            for (int half = 0; half < 2; half++) {
                int row = wn + half * 16 + (g >> 1) * 8 + r;
                int col = kk * 16 + (g & 1) * 8;
                ldsm_x4(bf[half * 2][0], bf[half * 2][1],
                        bf[half * 2 + 1][0], bf[half * 2 + 1][1],
                        sB + SW128((uint32_t)(row * 128 + col * 2)));
            }
            #pragma unroll
            for (int mi = 0; mi < 4; mi++)
                #pragma unroll
                for (int ni = 0; ni < 4; ni++)
                    mma_bf16(acc[mi][ni], af[mi], bf[ni]);
        }
        __syncthreads();
        if (c + 2 < NCHUNK) { issue_load(c & 1, c + 2); CP_COMMIT(); }
    }

    // ---- epilogue ----
    const int qrow = lane >> 2;
    const int qcol = (lane & 3) * 2;
    #pragma unroll
    for (int mi = 0; mi < 4; mi++) {
        #pragma unroll
        for (int ni = 0; ni < 4; ni++) {
            int row = bm + wm + mi * 16 + qrow;
            int col = bn + wn + ni * 8 + qcol;
            float b0 = ADD_BIAS ? bias[col]     : 0.0f;
            float b1 = ADD_BIAS ? bias[col + 1] : 0.0f;
            float2 v0 = { acc[mi][ni][0] + b0, acc[mi][ni][1] + b1 };
            float2 v1 = { acc[mi][ni][2] + b0, acc[mi][ni][3] + b1 };
            *reinterpret_cast<float2*>(C + (size_t)row * N4H + col) = v0;
            *reinterpret_cast<float2*>(C + (size_t)(row + 8) * N4H + col) = v1;
        }
    }
}

// ---------------- conversion kernels ----------------
__global__ __launch_bounds__(256) void conv_x_kernel(const float* __restrict__ X) {
    int idx = blockIdx.x * 256 + threadIdx.x;          // over 65536*512
    int m = idx >> 9, k = idx & 511;
    float v = X[idx];
    __nv_bfloat16 hi = __float2bfloat16(v);
    g_xhl[(size_t)m * KHL + k] = hi;
    g_xhl[(size_t)m * KHL + 512 + k] = __float2bfloat16(v - __bfloat162float(hi));
}

__global__ __launch_bounds__(256) void conv_w_kernel(const float* __restrict__ W,
                                                     __nv_bfloat16* __restrict__ Bt) {
    int idx = blockIdx.x * 256 + threadIdx.x;          // over 512*2048, W[k][n]
    int k = idx >> 11, n = idx & 2047;
    float v = W[idx];
    __nv_bfloat16 hi = __float2bfloat16(v);
    __nv_bfloat16 lo = __float2bfloat16(v - __bfloat162float(hi));
    Bt[(size_t)n * KBIG + k] = hi;
    Bt[(size_t)n * KBIG + 512 + k] = lo;
    Bt[(size_t)n * KBIG + 1024 + k] = hi;
}

// ---------------- fused gate / state update ----------------
__global__ __launch_bounds__(256) void lstm_step_kernel(int t, int has_h, float* __restrict__ out) {
    int idx = blockIdx.x * 256 + threadIdx.x;          // 0..B*H-1
    int b = idx >> 9;
    int k = idx & 511;

    size_t zx_base = ((size_t)b * TT + t) * N4H;
    float zi = g_zx[zx_base + 0 * HH + k];
    float zf = g_zx[zx_base + 1 * HH + k];
    float zg = g_zx[zx_base + 2 * HH + k];
    float zo = g_zx[zx_base + 3 * HH + k];
    float cp = 0.0f;
    if (has_h) {
        size_t zh = (size_t)b * N4H;
        zi += g_z[zh + 0 * HH + k];
        zf += g_z[zh + 1 * HH + k];
        zg += g_z[zh + 2 * HH + k];
        zo += g_z[zh + 3 * HH + k];
        cp = g_c[idx];
    }

    float i = 1.0f / (1.0f + expf(-zi));
    float f = 1.0f / (1.0f + expf(-zf));
    float g = tanhf(zg);
    float o = 1.0f / (1.0f + expf(-zo));

    float cn = f * cp + i * g;
    float hn = o * tanhf(cn);

    g_c[idx] = cn;
    out[((size_t)b * TT + t) * HH + k] = hn;

    __nv_bfloat16 hi = __float2bfloat16(hn);
    g_hhl[(size_t)b * KHL + k] = hi;
    g_hhl[(size_t)b * KHL + 512 + k] = __float2bfloat16(hn - __bfloat162float(hi));
}

// ---------------- launch ----------------
extern "C" void kernel_launch(void* const* d_in, const int* in_sizes, int n_in,
                              void* d_out, int out_size)
{
    const float* X    = (const float*)d_in[0];
    const float* W    = (const float*)d_in[1];
    const float* U    = (const float*)d_in[2];
    const float* bias = (const float*)d_in[3];
    float* out = (float*)d_out;

    float *zx_p, *z_p;
    __nv_bfloat16 *xhl_p, *wb_p, *ub_p, *hhl_p;
    cudaGetSymbolAddress((void**)&zx_p,  g_zx);
    cudaGetSymbolAddress((void**)&z_p,   g_z);
    cudaGetSymbolAddress((void**)&xhl_p, g_xhl);
    cudaGetSymbolAddress((void**)&wb_p,  g_wb);
    cudaGetSymbolAddress((void**)&ub_p,  g_ub);
    cudaGetSymbolAddress((void**)&hhl_p, g_hhl);

    const int SMEM = 2 * STAGE_BYTES + 1024;   // 66560
    cudaFuncSetAttribute(gemm3_kernel<true>,
                         cudaFuncAttributeMaxDynamicSharedMemorySize, SMEM);
    cudaFuncSetAttribute(gemm3_kernel<false>,
                         cudaFuncAttributeMaxDynamicSharedMemorySize, SMEM);

    // conversions
    conv_x_kernel<<<(65536 * 512) / 256, 256>>>(X);
    conv_w_kernel<<<(512 * 2048) / 256, 256>>>(W, wb_p);
    conv_w_kernel<<<(512 * 2048) / 256, 256>>>(U, ub_p);

    // Phase 1: Zx = X@W + bias  (M=65536, N=2048)
    gemm3_kernel<true><<<dim3(N4H / 128, 65536 / 128), 256, SMEM>>>(
        xhl_p, wb_p, bias, zx_p);

    const int elem_blocks = (BB * HH) / 256;
    lstm_step_kernel<<<elem_blocks, 256>>>(0, 0, out);

    // recurrence
    for (int t = 1; t < TT; t++) {
        gemm3_kernel<false><<<dim3(N4H / 128, BB / 128), 256, SMEM>>>(
            hhl_p, ub_p, nullptr, z_p);
        lstm_step_kernel<<<elem_blocks, 256>>>(t, 1, out);
    }
}